// round 15
// baseline (speedup 1.0000x reference)
#include <cuda_runtime.h>
#include <cuda_fp16.h>
#include <cstdint>

// Problem constants
#define B_   2
#define S_   4096
#define D_   1024
#define H_   16
#define DH_  64
#define DIL_ 4
#define L_   1024
#define R_   8192

// Scratch (device globals — no allocation allowed)
__device__ __half g_xrh[(size_t)R_ * D_];     // fp16, xr-permuted x
__device__ __half g_wh[4][(size_t)D_ * D_];   // fp16 Wq,Wk,Wv,Wf
__device__ __half g_qh[(size_t)R_ * D_];      // q pre-scaled by 0.125*log2(e)
__device__ __half g_kh[(size_t)R_ * D_];
__device__ __half g_vh[(size_t)R_ * D_];
__device__ __half g_ctxh[(size_t)R_ * D_];
__device__ float  g_atted[(size_t)R_ * D_];

// ---------------------------------------------------------------------------
// Helpers
// ---------------------------------------------------------------------------
__device__ __forceinline__ void mma_f16(float c[4], const uint32_t a[4],
                                        const uint32_t b0, const uint32_t b1) {
    asm volatile(
        "mma.sync.aligned.m16n8k16.row.col.f32.f16.f16.f32 "
        "{%0,%1,%2,%3}, {%4,%5,%6,%7}, {%8,%9}, {%0,%1,%2,%3};"
        : "+f"(c[0]), "+f"(c[1]), "+f"(c[2]), "+f"(c[3])
        : "r"(a[0]), "r"(a[1]), "r"(a[2]), "r"(a[3]), "r"(b0), "r"(b1));
}

__device__ __forceinline__ uint32_t smem_u32(const void* p) {
    uint32_t a;
    asm("{ .reg .u64 t; cvta.to.shared.u64 t, %1; cvt.u32.u64 %0, t; }"
        : "=r"(a) : "l"(p));
    return a;
}

__device__ __forceinline__ void cp16(uint32_t saddr, const void* gptr) {
    asm volatile("cp.async.cg.shared.global [%0], [%1], 16;"
                 :: "r"(saddr), "l"(gptr));
}
#define CP_COMMIT() asm volatile("cp.async.commit_group;" ::: "memory")
#define CP_WAIT(n)  asm volatile("cp.async.wait_group %0;" :: "n"(n) : "memory")

__device__ __forceinline__ void ldm_x4(uint32_t r[4], uint32_t saddr) {
    asm volatile("ldmatrix.sync.aligned.m8n8.x4.shared.b16 {%0,%1,%2,%3}, [%4];"
                 : "=r"(r[0]), "=r"(r[1]), "=r"(r[2]), "=r"(r[3])
                 : "r"(saddr));
}
__device__ __forceinline__ void ldm_x4t(uint32_t r[4], uint32_t saddr) {
    asm volatile("ldmatrix.sync.aligned.m8n8.x4.trans.shared.b16 {%0,%1,%2,%3}, [%4];"
                 : "=r"(r[0]), "=r"(r[1]), "=r"(r[2]), "=r"(r[3])
                 : "r"(saddr));
}
__device__ __forceinline__ float ex2(float x) {
    float y;
    asm("ex2.approx.f32 %0, %1;" : "=f"(y) : "f"(x));
    return y;
}
__device__ __forceinline__ uint32_t ex2h2(float lo, float hi) {
    half2 h = __floats2half2_rn(lo, hi);
    uint32_t y;
    asm("ex2.approx.f16x2 %0, %1;" : "=r"(y) : "r"(*(uint32_t*)&h));
    return y;
}

// ---------------------------------------------------------------------------
// Prep: fp16-round (+permute) x into g_xrh; fp16-round W's into g_wh.
// ---------------------------------------------------------------------------
__global__ void __launch_bounds__(256) prep_x(const float* __restrict__ x)
{
    const int idx = blockIdx.x * 256 + threadIdx.x;
    const int r  = idx >> 8;
    const int c4 = (idx & 255) * 4;
    const int bb = r >> 10, l = r & 1023;
    const int src = ((bb >> 2) << 12) + (l << 2) + (bb & 3);
    float4 v = *(const float4*)(x + (size_t)src * D_ + c4);
    half2 h0 = __floats2half2_rn(v.x, v.y);
    half2 h1 = __floats2half2_rn(v.z, v.w);
    uint2 u = make_uint2(*(uint32_t*)&h0, *(uint32_t*)&h1);
    *(uint2*)(g_xrh + (size_t)r * D_ + c4) = u;
}

__global__ void __launch_bounds__(256) prep_w(
    const float* __restrict__ Wq, const float* __restrict__ Wk,
    const float* __restrict__ Wv, const float* __restrict__ Wf)
{
    const float* src;
    switch (blockIdx.y) {
        case 0: src = Wq; break;
        case 1: src = Wk; break;
        case 2: src = Wv; break;
        default: src = Wf; break;
    }
    const size_t off = (size_t)blockIdx.x * 1024 + threadIdx.x * 4;
    float4 v = *(const float4*)(src + off);
    half2 h0 = __floats2half2_rn(v.x, v.y);
    half2 h1 = __floats2half2_rn(v.z, v.w);
    uint2 u = make_uint2(*(uint32_t*)&h0, *(uint32_t*)&h1);
    *(uint2*)(&g_wh[blockIdx.y][0] + off) = u;
}

// ---------------------------------------------------------------------------
// fp16 warp-MMA GEMM v3: CTA 128x128, 4 warps 2x2, warp tile 64x64,
// BK=64, 2-stage cp.async, 128 threads -> 2 CTAs/SM (CTA-level overlap).
// mode 0: A = g_xrh, W = g_wh[z], out = g_{q,k,v}h (q scaled 0.125*log2 e)
// mode 1: A = g_ctxh (x-order gather), W = g_wh[3], out = fp32 out_f32
// SMEM rows 144 B (conflict-free ldmatrix). Stage = (128+128)x144 = 36864 B,
// 2 stages = 73728 B per CTA.
// ---------------------------------------------------------------------------
#define GROWB 144
#define GATILE (128 * GROWB)
#define GSTAGE (2 * GATILE)
#define GEMM_SMEM (2 * GSTAGE)
#define QSCALE 0.180336880f   // (1/8) * log2(e)

__global__ void __launch_bounds__(128, 2) gemm_mma(
    const float* __restrict__ bq, const float* __restrict__ bk,
    const float* __restrict__ bv,
    float* __restrict__ out_f32, int mode)
{
    extern __shared__ char dsmc[];
    const uint32_t sb = smem_u32(dsmc);

    const int tid  = threadIdx.x;
    const int wid  = tid >> 5;
    const int lane = tid & 31;
    const int lr   = lane >> 2;
    const int lc   = lane & 3;
    const int l7   = lane & 7;
    const int lb8  = (lane >> 3) & 1;
    const int lb16 = lane >> 4;
    const int wm0  = (wid >> 1) * 64;   // 0 / 64
    const int wn0  = (wid & 1) * 64;    // 0 / 64

    const __half* A; const __half* W; const float* bias;
    __half* outh = nullptr;
    float qscale = 1.0f;
    if (mode == 0) {
        A = g_xrh;
        W = &g_wh[blockIdx.z][0];
        if (blockIdx.z == 0)      { bias = bq; outh = g_qh; qscale = QSCALE; }
        else if (blockIdx.z == 1) { bias = bk; outh = g_kh; }
        else                      { bias = bv; outh = g_vh; }
    } else {
        A = g_ctxh; W = &g_wh[3][0]; bias = bq;
    }

    const int rm0 = blockIdx.y * 128;
    const int on0 = blockIdx.x * 128;

    // staging: thread t owns A row t and B row t (8 cp16 each per chunk)
    int srcrow = rm0 + tid;
    if (mode == 1) {
        int b = srcrow >> 12, s = srcrow & 4095;
        srcrow = ((b << 2) + (s & 3)) * L_ + (s >> 2);
    }
    const __half* arow = A + (size_t)srcrow * D_;
    const __half* brow = W + (size_t)(on0 + tid) * D_;
    const uint32_t astso = (uint32_t)(tid * GROWB);
    const uint32_t bstso = (uint32_t)(GATILE + tid * GROWB);

    // fragment base offsets (16B-aligned, conflict-free)
    const uint32_t aoff = (uint32_t)((wm0 + l7 + lb8 * 8) * GROWB + lb16 * 16);
    const uint32_t boff = (uint32_t)(GATILE + (wn0 + lb16 * 8 + l7) * GROWB + lb8 * 16);

    // prologue: chunk 0 -> buffer 0
    #pragma unroll
    for (int j = 0; j < 8; j++) {
        cp16(sb + astso + j * 16, arow + j * 8);
        cp16(sb + bstso + j * 16, brow + j * 8);
    }
    CP_COMMIT();

    float acc[4][8][4] = {};

    for (int c = 0; c < 16; c++) {
        const int buf = c & 1;
        CP_WAIT(0);
        __syncthreads();   // chunk c visible; all warps done with buf (c-2)

        if (c < 15) {      // prefetch chunk c+1 into the other buffer
            const uint32_t ob = (uint32_t)(buf ^ 1) * GSTAGE;
            const int k1 = (c + 1) * 64;
            #pragma unroll
            for (int j = 0; j < 8; j++) {
                cp16(sb + ob + astso + j * 16, arow + k1 + j * 8);
                cp16(sb + ob + bstso + j * 16, brow + k1 + j * 8);
            }
            CP_COMMIT();
        }

        const uint32_t base = sb + (uint32_t)buf * GSTAGE;

        #pragma unroll
        for (int kk = 0; kk < 4; kk++) {
            uint32_t a[4][4], b[4][4];
            #pragma unroll
            for (int mf = 0; mf < 4; mf++)
                ldm_x4(a[mf], base + aoff + mf * 16 * GROWB + kk * 32);
            #pragma unroll
            for (int np = 0; np < 4; np++)
                ldm_x4(b[np], base + boff + np * 16 * GROWB + kk * 32);
            #pragma unroll
            for (int mf = 0; mf < 4; mf++)
                #pragma unroll
                for (int np = 0; np < 4; np++) {
                    mma_f16(acc[mf][2 * np],     a[mf], b[np][0], b[np][1]);
                    mma_f16(acc[mf][2 * np + 1], a[mf], b[np][2], b[np][3]);
                }
        }
        // no trailing sync: next iteration's top sync covers buffer reuse
    }

    #pragma unroll
    for (int mf = 0; mf < 4; mf++) {
        const int row0 = rm0 + wm0 + mf * 16 + lr;
        #pragma unroll
        for (int nf = 0; nf < 8; nf++) {
            const int col = on0 + wn0 + nf * 8 + 2 * lc;
            const float bx = bias[col], by = bias[col + 1];
            float o00 = acc[mf][nf][0] + bx, o01 = acc[mf][nf][1] + by;
            float o10 = acc[mf][nf][2] + bx, o11 = acc[mf][nf][3] + by;
            if (mode == 0) {
                o00 *= qscale; o01 *= qscale; o10 *= qscale; o11 *= qscale;
                *(half2*)(outh + (size_t)row0 * D_ + col) =
                    __floats2half2_rn(o00, o01);
                *(half2*)(outh + (size_t)(row0 + 8) * D_ + col) =
                    __floats2half2_rn(o10, o11);
            } else {
                *(float2*)(out_f32 + (size_t)row0 * D_ + col) =
                    make_float2(o00, o01);
                *(float2*)(out_f32 + (size_t)(row0 + 8) * D_ + col) =
                    make_float2(o10, o11);
            }
        }
    }
}

// ---------------------------------------------------------------------------
// fp16 attention (R13 exact — best known): FA2-style register P, 256 threads
// (8 warps), q-tile 128, key-tile 64 double-buffered, 2 CTAs/SM.
// SMEM: K0|K1|V0|V1 (64x144B each) + Q (128x144B) = 55296 B.
// ---------------------------------------------------------------------------
#define AROWB 144
#define KTB   (64 * AROWB)
#define QTB   (128 * AROWB)
#define QBASE (4 * KTB)
#define ATTN_SMEM (4 * KTB + QTB)

__global__ void __launch_bounds__(256, 2) attn_mma()
{
    extern __shared__ char dsmc[];
    const uint32_t sb = smem_u32(dsmc);

    const int tid  = threadIdx.x;
    const int wid  = tid >> 5;
    const int lane = tid & 31;
    const int lr   = lane >> 2;
    const int lc   = lane & 3;
    const int l7   = lane & 7;
    const int lb8  = (lane >> 3) & 1;
    const int lb16 = lane >> 4;
    const int bbh  = blockIdx.y;
    const int bb   = bbh >> 4;
    const int h    = bbh & 15;
    const int q0   = blockIdx.x * 128;

    const uint32_t ONES = 0x3C003C00u;   // half2(1.0, 1.0)

    const int krow = tid >> 2;
    const int kseg = tid & 3;
    const uint32_t kstg = (uint32_t)(krow * AROWB + kseg * 32);

    const __half* kg = g_kh + (size_t)(bb * L_) * D_ + h * DH_;
    const __half* vg = g_vh + (size_t)(bb * L_) * D_ + h * DH_;

    // prologue: K0/V0 in flight
    {
        const __half* kp = kg + (size_t)krow * D_ + kseg * 16;
        const __half* vp = vg + (size_t)krow * D_ + kseg * 16;
        cp16(sb + kstg, kp);
        cp16(sb + kstg + 16, kp + 8);
        cp16(sb + 2 * KTB + kstg, vp);
        cp16(sb + 2 * KTB + kstg + 16, vp + 8);
        CP_COMMIT();
    }

    // stage Q (128 x 64 halves, pre-scaled by 0.125*log2 e)
    {
        const int srow = tid >> 1;
        const __half* qg = g_qh + (size_t)(bb * L_ + q0 + srow) * D_ + h * DH_
                           + (tid & 1) * 32;
        char* dst = dsmc + QBASE + srow * AROWB + (tid & 1) * 64;
        #pragma unroll
        for (int j = 0; j < 4; j++)
            *(uint4*)(dst + j * 16) = *(const uint4*)(qg + j * 8);
    }
    __syncthreads();

    const uint32_t qoff = sb + QBASE
        + (uint32_t)((wid * 16 + l7 + lb8 * 8) * AROWB + lb16 * 16);
    const uint32_t koff = (uint32_t)((lb16 * 8 + l7) * AROWB + lb8 * 16);
    const uint32_t voff = (uint32_t)((l7 + lb8 * 8) * AROWB + lb16 * 16);

    uint32_t qa[4][4];
    #pragma unroll
    for (int kk = 0; kk < 4; kk++)
        ldm_x4(qa[kk], qoff + kk * 32);

    float O[8][4] = {};
    float lacc[4] = {};
    float m0 = -1e30f, m1 = -1e30f;

    for (int kt = 0; kt < 16; kt++) {
        const int buf = kt & 1;
        const uint32_t kbuf = sb + (uint32_t)buf * KTB;
        const uint32_t vbuf = sb + (uint32_t)(2 + buf) * KTB;

        CP_WAIT(0);
        __syncthreads();

        if (kt < 15) {
            const uint32_t ob = (uint32_t)(buf ^ 1) * KTB;
            const __half* kp = kg + (size_t)((kt + 1) * 64 + krow) * D_ + kseg * 16;
            const __half* vp = vg + (size_t)((kt + 1) * 64 + krow) * D_ + kseg * 16;
            cp16(sb + ob + kstg, kp);
            cp16(sb + ob + kstg + 16, kp + 8);
            cp16(sb + 2 * KTB + ob + kstg, vp);
            cp16(sb + 2 * KTB + ob + kstg + 16, vp + 8);
            CP_COMMIT();
        }

        // --- S = Qs @ K^T (16 x 64 per warp): 16 ldm + 32 MMA ---
        float s[8][4] = {};
        #pragma unroll
        for (int kk = 0; kk < 4; kk++) {
            #pragma unroll
            for (int np = 0; np < 4; np++) {
                uint32_t b[4];
                ldm_x4(b, kbuf + koff + (uint32_t)(np * 16 * AROWB + kk * 32));
                mma_f16(s[2 * np],     qa[kk], b[0], b[1]);
                mma_f16(s[2 * np + 1], qa[kk], b[2], b[3]);
            }
        }

        // --- online softmax (log2 domain), P kept in registers ---
        float ml0 = -1e30f, ml1 = -1e30f;
        #pragma unroll
        for (int nf = 0; nf < 8; nf++) {
            ml0 = fmaxf(ml0, fmaxf(s[nf][0], s[nf][1]));
            ml1 = fmaxf(ml1, fmaxf(s[nf][2], s[nf][3]));
        }
        ml0 = fmaxf(ml0, __shfl_xor_sync(0xffffffffu, ml0, 1));
        ml0 = fmaxf(ml0, __shfl_xor_sync(0xffffffffu, ml0, 2));
        ml1 = fmaxf(ml1, __shfl_xor_sync(0xffffffffu, ml1, 1));
        ml1 = fmaxf(ml1, __shfl_xor_sync(0xffffffffu, ml1, 2));
        const float mn0 = fmaxf(m0, ml0), mn1 = fmaxf(m1, ml1);
        const float c0 = ex2(m0 - mn0), c1 = ex2(m1 - mn1);
        m0 = mn0; m1 = mn1;

        uint32_t pl[8], ph[8];
        #pragma unroll
        for (int nf = 0; nf < 8; nf++) {
            pl[nf] = ex2h2(s[nf][0] - mn0, s[nf][1] - mn0);
            ph[nf] = ex2h2(s[nf][2] - mn1, s[nf][3] - mn1);
        }

        lacc[0] *= c0; lacc[1] *= c0; lacc[2] *= c1; lacc[3] *= c1;
        #pragma unroll
        for (int nf = 0; nf < 8; nf++) {
            O[nf][0] *= c0; O[nf][1] *= c0;
            O[nf][2] *= c1; O[nf][3] *= c1;
        }

        // --- l += P @ ones ---
        #pragma unroll
        for (int kk = 0; kk < 4; kk++) {
            const uint32_t a[4] = {pl[2*kk], ph[2*kk], pl[2*kk+1], ph[2*kk+1]};
            mma_f16(lacc, a, ONES, ONES);
        }

        // --- O += P @ V ---
        #pragma unroll
        for (int kk = 0; kk < 4; kk++) {
            const uint32_t a[4] = {pl[2*kk], ph[2*kk], pl[2*kk+1], ph[2*kk+1]};
            #pragma unroll
            for (int np = 0; np < 4; np++) {
                uint32_t b[4];
                ldm_x4t(b, vbuf + voff + (uint32_t)(kk * 16 * AROWB + np * 32));
                mma_f16(O[2 * np],     a, b[0], b[1]);
                mma_f16(O[2 * np + 1], a, b[2], b[3]);
            }
        }
    }

    const float inv0 = 1.f / lacc[0], inv1 = 1.f / lacc[2];
    __half* og = g_ctxh + (size_t)(bb * L_ + q0 + wid * 16) * D_ + h * DH_;
    #pragma unroll
    for (int nf = 0; nf < 8; nf++) {
        const int col = nf * 8 + 2 * lc;
        *(half2*)(og + (size_t)lr * D_ + col) =
            __floats2half2_rn(O[nf][0] * inv0, O[nf][1] * inv0);
        *(half2*)(og + (size_t)(lr + 8) * D_ + col) =
            __floats2half2_rn(O[nf][2] * inv1, O[nf][3] * inv1);
    }
}

// ---------------------------------------------------------------------------
// final = LayerNorm(atted + x) * gamma + beta.
// ---------------------------------------------------------------------------
__global__ void __launch_bounds__(256) ln_kernel(
    const float* __restrict__ x,
    const float* __restrict__ atted_ext,
    const float* __restrict__ gamma, const float* __restrict__ beta,
    float* __restrict__ final_out)
{
    const float* atted = atted_ext;
    const int r = blockIdx.x;
    const float* xa = x     + (size_t)r * D_;
    const float* aa = atted + (size_t)r * D_;
    const int tid = threadIdx.x;

    float v[4];
    float s1 = 0.f, s2 = 0.f;
    #pragma unroll
    for (int i = 0; i < 4; i++) {
        int c = tid + i * 256;
        float val = xa[c] + aa[c];
        v[i] = val;
        s1 += val; s2 += val * val;
    }
    #pragma unroll
    for (int off = 16; off; off >>= 1) {
        s1 += __shfl_xor_sync(0xffffffffu, s1, off);
        s2 += __shfl_xor_sync(0xffffffffu, s2, off);
    }
    __shared__ float red[16];
    int warp = tid >> 5, lane = tid & 31;
    if (lane == 0) { red[warp] = s1; red[8 + warp] = s2; }
    __syncthreads();
    float t1 = 0.f, t2 = 0.f;
    #pragma unroll
    for (int w = 0; w < 8; w++) { t1 += red[w]; t2 += red[8 + w]; }
    float mu  = t1 * (1.f / 1024.f);
    float var = t2 * (1.f / 1024.f) - mu * mu;
    float rstd = rsqrtf(var + 1e-5f);
    #pragma unroll
    for (int i = 0; i < 4; i++) {
        int c = tid + i * 256;
        final_out[(size_t)r * D_ + c] = (v[i] - mu) * rstd * gamma[c] + beta[c];
    }
}

// ---------------------------------------------------------------------------
extern "C" void kernel_launch(void* const* d_in, const int* in_sizes, int n_in,
                              void* d_out, int out_size)
{
    (void)in_sizes; (void)n_in;
    const float* x     = (const float*)d_in[0];
    const float* Wq    = (const float*)d_in[1];
    const float* bq    = (const float*)d_in[2];
    const float* Wk    = (const float*)d_in[3];
    const float* bk    = (const float*)d_in[4];
    const float* Wv    = (const float*)d_in[5];
    const float* bv    = (const float*)d_in[6];
    const float* Wf    = (const float*)d_in[7];
    const float* bf    = (const float*)d_in[8];
    const float* gamma = (const float*)d_in[9];
    const float* beta  = (const float*)d_in[10];
    float* out = (float*)d_out;

    const long long both = 2LL * R_ * D_;
    float* atted = (out_size >= both) ? (out + (size_t)R_ * D_) : nullptr;
    if (!atted) {
        static float* h_atted_ptr = nullptr;
        if (!h_atted_ptr) cudaGetSymbolAddress((void**)&h_atted_ptr, g_atted);
        atted = h_atted_ptr;
    }

    static bool attr_set = false;
    if (!attr_set) {
        cudaFuncSetAttribute(attn_mma,
                             cudaFuncAttributeMaxDynamicSharedMemorySize,
                             ATTN_SMEM);
        cudaFuncSetAttribute(gemm_mma,
                             cudaFuncAttributeMaxDynamicSharedMemorySize,
                             GEMM_SMEM);
        attr_set = true;
    }

    prep_x<<<R_ * D_ / 1024, 256>>>(x);
    prep_w<<<dim3(D_ * D_ / 1024, 4), 256>>>(Wq, Wk, Wv, Wf);

    gemm_mma<<<dim3(D_/128, R_/128, 3), 128, GEMM_SMEM>>>(
        bq, bk, bv, nullptr, 0);
    attn_mma<<<dim3(L_/128, B_ * DIL_ * H_), 256, ATTN_SMEM>>>();
    gemm_mma<<<dim3(D_/128, R_/128, 1), 128, GEMM_SMEM>>>(
        bf, nullptr, nullptr, atted, 1);
    ln_kernel<<<R_, 256>>>(x, atted, gamma, beta, out);
}

// round 16
// speedup vs baseline: 1.2308x; 1.2308x over previous
#include <cuda_runtime.h>
#include <cuda_fp16.h>
#include <cstdint>

// Problem constants
#define B_   2
#define S_   4096
#define D_   1024
#define H_   16
#define DH_  64
#define DIL_ 4
#define L_   1024
#define R_   8192

// Scratch (device globals — no allocation allowed)
__device__ __half g_xrh[(size_t)R_ * D_];     // fp16, xr-permuted x
__device__ __half g_wh[4][(size_t)D_ * D_];   // fp16 Wq,Wk,Wv,Wf
__device__ __half g_qh[(size_t)R_ * D_];      // q pre-scaled by 0.125*log2(e)
__device__ __half g_kh[(size_t)R_ * D_];
__device__ __half g_vh[(size_t)R_ * D_];
__device__ __half g_ctxh[(size_t)R_ * D_];
__device__ float  g_atted[(size_t)R_ * D_];

// ---------------------------------------------------------------------------
// Helpers
// ---------------------------------------------------------------------------
__device__ __forceinline__ void mma_f16(float c[4], const uint32_t a[4],
                                        const uint32_t b0, const uint32_t b1) {
    asm volatile(
        "mma.sync.aligned.m16n8k16.row.col.f32.f16.f16.f32 "
        "{%0,%1,%2,%3}, {%4,%5,%6,%7}, {%8,%9}, {%0,%1,%2,%3};"
        : "+f"(c[0]), "+f"(c[1]), "+f"(c[2]), "+f"(c[3])
        : "r"(a[0]), "r"(a[1]), "r"(a[2]), "r"(a[3]), "r"(b0), "r"(b1));
}

__device__ __forceinline__ uint32_t smem_u32(const void* p) {
    uint32_t a;
    asm("{ .reg .u64 t; cvta.to.shared.u64 t, %1; cvt.u32.u64 %0, t; }"
        : "=r"(a) : "l"(p));
    return a;
}

__device__ __forceinline__ void cp16(uint32_t saddr, const void* gptr) {
    asm volatile("cp.async.ca.shared.global [%0], [%1], 16;"
                 :: "r"(saddr), "l"(gptr));
}
#define CP_COMMIT() asm volatile("cp.async.commit_group;" ::: "memory")
#define CP_WAIT(n)  asm volatile("cp.async.wait_group %0;" :: "n"(n) : "memory")

__device__ __forceinline__ void ldm_x4(uint32_t r[4], uint32_t saddr) {
    asm volatile("ldmatrix.sync.aligned.m8n8.x4.shared.b16 {%0,%1,%2,%3}, [%4];"
                 : "=r"(r[0]), "=r"(r[1]), "=r"(r[2]), "=r"(r[3])
                 : "r"(saddr));
}
__device__ __forceinline__ void ldm_x4t(uint32_t r[4], uint32_t saddr) {
    asm volatile("ldmatrix.sync.aligned.m8n8.x4.trans.shared.b16 {%0,%1,%2,%3}, [%4];"
                 : "=r"(r[0]), "=r"(r[1]), "=r"(r[2]), "=r"(r[3])
                 : "r"(saddr));
}
__device__ __forceinline__ float ex2(float x) {
    float y;
    asm("ex2.approx.f32 %0, %1;" : "=f"(y) : "f"(x));
    return y;
}
__device__ __forceinline__ uint32_t ex2h2(float lo, float hi) {
    half2 h = __floats2half2_rn(lo, hi);
    uint32_t y;
    asm("ex2.approx.f16x2 %0, %1;" : "=r"(y) : "r"(*(uint32_t*)&h));
    return y;
}

// ---------------------------------------------------------------------------
// Merged prep: blocks [0, 8192) round+permute x -> g_xrh;
// blocks [8192, 12288) round Wq/Wk/Wv/Wf -> g_wh.  One launch.
// ---------------------------------------------------------------------------
__global__ void __launch_bounds__(256) prep_all(
    const float* __restrict__ x,
    const float* __restrict__ Wq, const float* __restrict__ Wk,
    const float* __restrict__ Wv, const float* __restrict__ Wf)
{
    const int bid = blockIdx.x;
    const int tid = threadIdx.x;
    if (bid < 8192) {
        const int idx = bid * 256 + tid;
        const int r  = idx >> 8;
        const int c4 = (idx & 255) * 4;
        const int bb = r >> 10, l = r & 1023;
        const int src = ((bb >> 2) << 12) + (l << 2) + (bb & 3);
        float4 v = *(const float4*)(x + (size_t)src * D_ + c4);
        half2 h0 = __floats2half2_rn(v.x, v.y);
        half2 h1 = __floats2half2_rn(v.z, v.w);
        uint2 u = make_uint2(*(uint32_t*)&h0, *(uint32_t*)&h1);
        *(uint2*)(g_xrh + (size_t)r * D_ + c4) = u;
    } else {
        const int wb  = bid - 8192;
        const int mat = wb >> 10;        // 0..3
        const int blk = wb & 1023;
        const float* src;
        switch (mat) {
            case 0: src = Wq; break;
            case 1: src = Wk; break;
            case 2: src = Wv; break;
            default: src = Wf; break;
        }
        const size_t off = (size_t)blk * 1024 + tid * 4;
        float4 v = *(const float4*)(src + off);
        half2 h0 = __floats2half2_rn(v.x, v.y);
        half2 h1 = __floats2half2_rn(v.z, v.w);
        uint2 u = make_uint2(*(uint32_t*)&h0, *(uint32_t*)&h1);
        *(uint2*)(&g_wh[mat][0] + off) = u;
    }
}

// ---------------------------------------------------------------------------
// fp16 warp-MMA GEMM (R13 exact): CTA 256x128, 8 warps 4x2, warp 64x64,
// BK=64, 2-stage cp.async. q epilogue scale = 0.125*log2(e).
// ---------------------------------------------------------------------------
#define GROWB 144
#define ATILE (256 * GROWB)
#define BTILE (128 * GROWB)
#define STAGE (ATILE + BTILE)
#define GEMM_SMEM (2 * STAGE)
#define QSCALE 0.180336880f   // (1/8) * log2(e)

__global__ void __launch_bounds__(256, 1) gemm_mma(
    const float* __restrict__ bq, const float* __restrict__ bk,
    const float* __restrict__ bv,
    float* __restrict__ out_f32, int mode)
{
    extern __shared__ char dsmc[];
    const uint32_t sb = smem_u32(dsmc);

    const int tid  = threadIdx.x;
    const int wid  = tid >> 5;
    const int lane = tid & 31;
    const int lr   = lane >> 2;
    const int lc   = lane & 3;
    const int l7   = lane & 7;
    const int lb8  = (lane >> 3) & 1;
    const int lb16 = lane >> 4;
    const int wm0  = (wid >> 1) * 64;
    const int wn0  = (wid & 1) * 64;

    const __half* A; const __half* W; const float* bias;
    __half* outh = nullptr;
    float qscale = 1.0f;
    if (mode == 0) {
        A = g_xrh;
        W = &g_wh[blockIdx.z][0];
        if (blockIdx.z == 0)      { bias = bq; outh = g_qh; qscale = QSCALE; }
        else if (blockIdx.z == 1) { bias = bk; outh = g_kh; }
        else                      { bias = bv; outh = g_vh; }
    } else {
        A = g_ctxh; W = &g_wh[3][0]; bias = bq;
    }

    const int rm0 = blockIdx.y * 256;
    const int on0 = blockIdx.x * 128;

    const int strow = tid >> 1;
    const int seg   = tid & 1;
    const __half* arow[2];
    uint32_t astso[2];
    #pragma unroll
    for (int p = 0; p < 2; p++) {
        int r = rm0 + p * 128 + strow;
        int srcrow = r;
        if (mode == 1) {
            int b = r >> 12, s = r & 4095;
            srcrow = ((b << 2) + (s & 3)) * L_ + (s >> 2);
        }
        arow[p]  = A + (size_t)srcrow * D_ + seg * 32;
        astso[p] = (uint32_t)((p * 128 + strow) * GROWB + seg * 64);
    }
    const __half* brow = W + (size_t)(on0 + strow) * D_ + seg * 32;
    const uint32_t bstso = (uint32_t)(ATILE + strow * GROWB + seg * 64);

    const uint32_t aoff = (uint32_t)((wm0 + l7 + lb8 * 8) * GROWB + lb16 * 16);
    const uint32_t boff = (uint32_t)(ATILE + (wn0 + lb16 * 8 + l7) * GROWB + lb8 * 16);

    // prologue: chunk 0 -> buffer 0
    #pragma unroll
    for (int j = 0; j < 4; j++) {
        cp16(sb + astso[0] + j * 16, arow[0] + j * 8);
        cp16(sb + astso[1] + j * 16, arow[1] + j * 8);
        cp16(sb + bstso + j * 16, brow + j * 8);
    }
    CP_COMMIT();

    float acc[4][8][4] = {};

    for (int c = 0; c < 16; c++) {
        const int buf = c & 1;
        CP_WAIT(0);
        __syncthreads();   // chunk c visible; all warps done with buf (c-2)

        if (c < 15) {      // prefetch chunk c+1 into the other buffer
            const uint32_t ob = (uint32_t)(buf ^ 1) * STAGE;
            const int k1 = (c + 1) * 64;
            #pragma unroll
            for (int j = 0; j < 4; j++) {
                cp16(sb + ob + astso[0] + j * 16, arow[0] + k1 + j * 8);
                cp16(sb + ob + astso[1] + j * 16, arow[1] + k1 + j * 8);
                cp16(sb + ob + bstso + j * 16, brow + k1 + j * 8);
            }
            CP_COMMIT();
        }

        const uint32_t base = sb + (uint32_t)buf * STAGE;

        #pragma unroll
        for (int kk = 0; kk < 4; kk++) {
            uint32_t a[4][4], b[4][4];
            #pragma unroll
            for (int mf = 0; mf < 4; mf++)
                ldm_x4(a[mf], base + aoff + mf * 16 * GROWB + kk * 32);
            #pragma unroll
            for (int np = 0; np < 4; np++)
                ldm_x4(b[np], base + boff + np * 16 * GROWB + kk * 32);
            #pragma unroll
            for (int mf = 0; mf < 4; mf++)
                #pragma unroll
                for (int np = 0; np < 4; np++) {
                    mma_f16(acc[mf][2 * np],     a[mf], b[np][0], b[np][1]);
                    mma_f16(acc[mf][2 * np + 1], a[mf], b[np][2], b[np][3]);
                }
        }
        // no trailing sync: next iteration's top sync covers buffer reuse
    }

    #pragma unroll
    for (int mf = 0; mf < 4; mf++) {
        const int row0 = rm0 + wm0 + mf * 16 + lr;
        #pragma unroll
        for (int nf = 0; nf < 8; nf++) {
            const int col = on0 + wn0 + nf * 8 + 2 * lc;
            const float bx = bias[col], by = bias[col + 1];
            float o00 = acc[mf][nf][0] + bx, o01 = acc[mf][nf][1] + by;
            float o10 = acc[mf][nf][2] + bx, o11 = acc[mf][nf][3] + by;
            if (mode == 0) {
                o00 *= qscale; o01 *= qscale; o10 *= qscale; o11 *= qscale;
                *(half2*)(outh + (size_t)row0 * D_ + col) =
                    __floats2half2_rn(o00, o01);
                *(half2*)(outh + (size_t)(row0 + 8) * D_ + col) =
                    __floats2half2_rn(o10, o11);
            } else {
                *(float2*)(out_f32 + (size_t)row0 * D_ + col) =
                    make_float2(o00, o01);
                *(float2*)(out_f32 + (size_t)(row0 + 8) * D_ + col) =
                    make_float2(o10, o11);
            }
        }
    }
}

// ---------------------------------------------------------------------------
// fp16 attention (R13 exact): FA2-style register P, 256 threads (8 warps),
// q-tile 128, key-tile 64 double-buffered, 2 CTAs/SM.
// SMEM: K0|K1|V0|V1 (64x144B each) + Q (128x144B) = 55296 B.
// ---------------------------------------------------------------------------
#define AROWB 144
#define KTB   (64 * AROWB)
#define QTB   (128 * AROWB)
#define QBASE (4 * KTB)
#define ATTN_SMEM (4 * KTB + QTB)

__global__ void __launch_bounds__(256, 2) attn_mma()
{
    extern __shared__ char dsmc[];
    const uint32_t sb = smem_u32(dsmc);

    const int tid  = threadIdx.x;
    const int wid  = tid >> 5;
    const int lane = tid & 31;
    const int lr   = lane >> 2;
    const int lc   = lane & 3;
    const int l7   = lane & 7;
    const int lb8  = (lane >> 3) & 1;
    const int lb16 = lane >> 4;
    const int bbh  = blockIdx.y;
    const int bb   = bbh >> 4;
    const int h    = bbh & 15;
    const int q0   = blockIdx.x * 128;

    const uint32_t ONES = 0x3C003C00u;   // half2(1.0, 1.0)

    const int krow = tid >> 2;
    const int kseg = tid & 3;
    const uint32_t kstg = (uint32_t)(krow * AROWB + kseg * 32);

    const __half* kg = g_kh + (size_t)(bb * L_) * D_ + h * DH_;
    const __half* vg = g_vh + (size_t)(bb * L_) * D_ + h * DH_;

    // prologue: K0/V0 in flight
    {
        const __half* kp = kg + (size_t)krow * D_ + kseg * 16;
        const __half* vp = vg + (size_t)krow * D_ + kseg * 16;
        cp16(sb + kstg, kp);
        cp16(sb + kstg + 16, kp + 8);
        cp16(sb + 2 * KTB + kstg, vp);
        cp16(sb + 2 * KTB + kstg + 16, vp + 8);
        CP_COMMIT();
    }

    // stage Q (128 x 64 halves, pre-scaled by 0.125*log2 e)
    {
        const int srow = tid >> 1;
        const __half* qg = g_qh + (size_t)(bb * L_ + q0 + srow) * D_ + h * DH_
                           + (tid & 1) * 32;
        char* dst = dsmc + QBASE + srow * AROWB + (tid & 1) * 64;
        #pragma unroll
        for (int j = 0; j < 4; j++)
            *(uint4*)(dst + j * 16) = *(const uint4*)(qg + j * 8);
    }
    __syncthreads();

    const uint32_t qoff = sb + QBASE
        + (uint32_t)((wid * 16 + l7 + lb8 * 8) * AROWB + lb16 * 16);
    const uint32_t koff = (uint32_t)((lb16 * 8 + l7) * AROWB + lb8 * 16);
    const uint32_t voff = (uint32_t)((l7 + lb8 * 8) * AROWB + lb16 * 16);

    uint32_t qa[4][4];
    #pragma unroll
    for (int kk = 0; kk < 4; kk++)
        ldm_x4(qa[kk], qoff + kk * 32);

    float O[8][4] = {};
    float lacc[4] = {};
    float m0 = -1e30f, m1 = -1e30f;

    for (int kt = 0; kt < 16; kt++) {
        const int buf = kt & 1;
        const uint32_t kbuf = sb + (uint32_t)buf * KTB;
        const uint32_t vbuf = sb + (uint32_t)(2 + buf) * KTB;

        CP_WAIT(0);
        __syncthreads();

        if (kt < 15) {
            const uint32_t ob = (uint32_t)(buf ^ 1) * KTB;
            const __half* kp = kg + (size_t)((kt + 1) * 64 + krow) * D_ + kseg * 16;
            const __half* vp = vg + (size_t)((kt + 1) * 64 + krow) * D_ + kseg * 16;
            cp16(sb + ob + kstg, kp);
            cp16(sb + ob + kstg + 16, kp + 8);
            cp16(sb + 2 * KTB + ob + kstg, vp);
            cp16(sb + 2 * KTB + ob + kstg + 16, vp + 8);
            CP_COMMIT();
        }

        // --- S = Qs @ K^T (16 x 64 per warp): 16 ldm + 32 MMA ---
        float s[8][4] = {};
        #pragma unroll
        for (int kk = 0; kk < 4; kk++) {
            #pragma unroll
            for (int np = 0; np < 4; np++) {
                uint32_t b[4];
                ldm_x4(b, kbuf + koff + (uint32_t)(np * 16 * AROWB + kk * 32));
                mma_f16(s[2 * np],     qa[kk], b[0], b[1]);
                mma_f16(s[2 * np + 1], qa[kk], b[2], b[3]);
            }
        }

        // --- online softmax (log2 domain), P kept in registers ---
        float ml0 = -1e30f, ml1 = -1e30f;
        #pragma unroll
        for (int nf = 0; nf < 8; nf++) {
            ml0 = fmaxf(ml0, fmaxf(s[nf][0], s[nf][1]));
            ml1 = fmaxf(ml1, fmaxf(s[nf][2], s[nf][3]));
        }
        ml0 = fmaxf(ml0, __shfl_xor_sync(0xffffffffu, ml0, 1));
        ml0 = fmaxf(ml0, __shfl_xor_sync(0xffffffffu, ml0, 2));
        ml1 = fmaxf(ml1, __shfl_xor_sync(0xffffffffu, ml1, 1));
        ml1 = fmaxf(ml1, __shfl_xor_sync(0xffffffffu, ml1, 2));
        const float mn0 = fmaxf(m0, ml0), mn1 = fmaxf(m1, ml1);
        const float c0 = ex2(m0 - mn0), c1 = ex2(m1 - mn1);
        m0 = mn0; m1 = mn1;

        uint32_t pl[8], ph[8];
        #pragma unroll
        for (int nf = 0; nf < 8; nf++) {
            pl[nf] = ex2h2(s[nf][0] - mn0, s[nf][1] - mn0);
            ph[nf] = ex2h2(s[nf][2] - mn1, s[nf][3] - mn1);
        }

        lacc[0] *= c0; lacc[1] *= c0; lacc[2] *= c1; lacc[3] *= c1;
        #pragma unroll
        for (int nf = 0; nf < 8; nf++) {
            O[nf][0] *= c0; O[nf][1] *= c0;
            O[nf][2] *= c1; O[nf][3] *= c1;
        }

        // --- l += P @ ones ---
        #pragma unroll
        for (int kk = 0; kk < 4; kk++) {
            const uint32_t a[4] = {pl[2*kk], ph[2*kk], pl[2*kk+1], ph[2*kk+1]};
            mma_f16(lacc, a, ONES, ONES);
        }

        // --- O += P @ V ---
        #pragma unroll
        for (int kk = 0; kk < 4; kk++) {
            const uint32_t a[4] = {pl[2*kk], ph[2*kk], pl[2*kk+1], ph[2*kk+1]};
            #pragma unroll
            for (int np = 0; np < 4; np++) {
                uint32_t b[4];
                ldm_x4t(b, vbuf + voff + (uint32_t)(kk * 16 * AROWB + np * 32));
                mma_f16(O[2 * np],     a, b[0], b[1]);
                mma_f16(O[2 * np + 1], a, b[2], b[3]);
            }
        }
    }

    const float inv0 = 1.f / lacc[0], inv1 = 1.f / lacc[2];
    __half* og = g_ctxh + (size_t)(bb * L_ + q0 + wid * 16) * D_ + h * DH_;
    #pragma unroll
    for (int nf = 0; nf < 8; nf++) {
        const int col = nf * 8 + 2 * lc;
        *(half2*)(og + (size_t)lr * D_ + col) =
            __floats2half2_rn(O[nf][0] * inv0, O[nf][1] * inv0);
        *(half2*)(og + (size_t)(lr + 8) * D_ + col) =
            __floats2half2_rn(O[nf][2] * inv1, O[nf][3] * inv1);
    }
}

// ---------------------------------------------------------------------------
// final = LayerNorm(atted + x) * gamma + beta.  float4 I/O version.
// ---------------------------------------------------------------------------
__global__ void __launch_bounds__(256) ln_kernel(
    const float* __restrict__ x,
    const float* __restrict__ atted_ext,
    const float* __restrict__ gamma, const float* __restrict__ beta,
    float* __restrict__ final_out)
{
    const float* atted = atted_ext;
    const int r = blockIdx.x;
    const int tid = threadIdx.x;
    const size_t base = (size_t)r * D_ + tid * 4;

    float4 xv = *(const float4*)(x + base);
    float4 av = *(const float4*)(atted + base);
    float4 v = make_float4(xv.x + av.x, xv.y + av.y, xv.z + av.z, xv.w + av.w);
    float s1 = v.x + v.y + v.z + v.w;
    float s2 = v.x*v.x + v.y*v.y + v.z*v.z + v.w*v.w;

    #pragma unroll
    for (int off = 16; off; off >>= 1) {
        s1 += __shfl_xor_sync(0xffffffffu, s1, off);
        s2 += __shfl_xor_sync(0xffffffffu, s2, off);
    }
    __shared__ float red[16];
    int warp = tid >> 5, lane = tid & 31;
    if (lane == 0) { red[warp] = s1; red[8 + warp] = s2; }
    __syncthreads();
    float t1 = 0.f, t2 = 0.f;
    #pragma unroll
    for (int w = 0; w < 8; w++) { t1 += red[w]; t2 += red[8 + w]; }
    float mu  = t1 * (1.f / 1024.f);
    float var = t2 * (1.f / 1024.f) - mu * mu;
    float rstd = rsqrtf(var + 1e-5f);

    float4 gv = *(const float4*)(gamma + tid * 4);
    float4 bv = *(const float4*)(beta + tid * 4);
    float4 o;
    o.x = (v.x - mu) * rstd * gv.x + bv.x;
    o.y = (v.y - mu) * rstd * gv.y + bv.y;
    o.z = (v.z - mu) * rstd * gv.z + bv.z;
    o.w = (v.w - mu) * rstd * gv.w + bv.w;
    *(float4*)(final_out + base) = o;
}

// ---------------------------------------------------------------------------
extern "C" void kernel_launch(void* const* d_in, const int* in_sizes, int n_in,
                              void* d_out, int out_size)
{
    (void)in_sizes; (void)n_in;
    const float* x     = (const float*)d_in[0];
    const float* Wq    = (const float*)d_in[1];
    const float* bq    = (const float*)d_in[2];
    const float* Wk    = (const float*)d_in[3];
    const float* bk    = (const float*)d_in[4];
    const float* Wv    = (const float*)d_in[5];
    const float* bv    = (const float*)d_in[6];
    const float* Wf    = (const float*)d_in[7];
    const float* bf    = (const float*)d_in[8];
    const float* gamma = (const float*)d_in[9];
    const float* beta  = (const float*)d_in[10];
    float* out = (float*)d_out;

    const long long both = 2LL * R_ * D_;
    float* atted = (out_size >= both) ? (out + (size_t)R_ * D_) : nullptr;
    if (!atted) {
        static float* h_atted_ptr = nullptr;
        if (!h_atted_ptr) cudaGetSymbolAddress((void**)&h_atted_ptr, g_atted);
        atted = h_atted_ptr;
    }

    static bool attr_set = false;
    if (!attr_set) {
        cudaFuncSetAttribute(attn_mma,
                             cudaFuncAttributeMaxDynamicSharedMemorySize,
                             ATTN_SMEM);
        cudaFuncSetAttribute(gemm_mma,
                             cudaFuncAttributeMaxDynamicSharedMemorySize,
                             GEMM_SMEM);
        attr_set = true;
    }

    // Prep (one launch): x permute+round, W rounds.
    prep_all<<<R_ * D_ / 1024 + 4 * D_ * D_ / 1024, 256>>>(x, Wq, Wk, Wv, Wf);

    gemm_mma<<<dim3(D_/128, R_/256, 3), 256, GEMM_SMEM>>>(
        bq, bk, bv, nullptr, 0);
    attn_mma<<<dim3(L_/128, B_ * DIL_ * H_), 256, ATTN_SMEM>>>();
    gemm_mma<<<dim3(D_/128, R_/256, 1), 256, GEMM_SMEM>>>(
        bf, nullptr, nullptr, atted, 1);
    ln_kernel<<<R_, 256>>>(x, atted, gamma, beta, out);
}

// round 17
// speedup vs baseline: 1.4520x; 1.1797x over previous
#include <cuda_runtime.h>
#include <cuda_fp16.h>
#include <cstdint>

// Problem constants
#define B_   2
#define S_   4096
#define D_   1024
#define H_   16
#define DH_  64
#define DIL_ 4
#define L_   1024
#define R_   8192

// Scratch (device globals — no allocation allowed)
__device__ __half g_xrh[(size_t)R_ * D_];     // fp16, xr-permuted x
__device__ __half g_wh[4][(size_t)D_ * D_];   // fp16 Wq,Wk,Wv,Wf
__device__ __half g_qh[(size_t)R_ * D_];      // q pre-scaled by 0.125*log2(e)
__device__ __half g_kh[(size_t)R_ * D_];
__device__ __half g_vh[(size_t)R_ * D_];
__device__ __half g_ctxh[(size_t)R_ * D_];
__device__ float  g_atted[(size_t)R_ * D_];

// ---------------------------------------------------------------------------
// Helpers
// ---------------------------------------------------------------------------
__device__ __forceinline__ void mma_f16(float c[4], const uint32_t a[4],
                                        const uint32_t b0, const uint32_t b1) {
    asm volatile(
        "mma.sync.aligned.m16n8k16.row.col.f32.f16.f16.f32 "
        "{%0,%1,%2,%3}, {%4,%5,%6,%7}, {%8,%9}, {%0,%1,%2,%3};"
        : "+f"(c[0]), "+f"(c[1]), "+f"(c[2]), "+f"(c[3])
        : "r"(a[0]), "r"(a[1]), "r"(a[2]), "r"(a[3]), "r"(b0), "r"(b1));
}

__device__ __forceinline__ uint32_t smem_u32(const void* p) {
    uint32_t a;
    asm("{ .reg .u64 t; cvta.to.shared.u64 t, %1; cvt.u32.u64 %0, t; }"
        : "=r"(a) : "l"(p));
    return a;
}

__device__ __forceinline__ void cp16(uint32_t saddr, const void* gptr) {
    asm volatile("cp.async.ca.shared.global [%0], [%1], 16;"
                 :: "r"(saddr), "l"(gptr));
}
#define CP_COMMIT() asm volatile("cp.async.commit_group;" ::: "memory")
#define CP_WAIT(n)  asm volatile("cp.async.wait_group %0;" :: "n"(n) : "memory")

__device__ __forceinline__ void ldm_x4(uint32_t r[4], uint32_t saddr) {
    asm volatile("ldmatrix.sync.aligned.m8n8.x4.shared.b16 {%0,%1,%2,%3}, [%4];"
                 : "=r"(r[0]), "=r"(r[1]), "=r"(r[2]), "=r"(r[3])
                 : "r"(saddr));
}
__device__ __forceinline__ void ldm_x4t(uint32_t r[4], uint32_t saddr) {
    asm volatile("ldmatrix.sync.aligned.m8n8.x4.trans.shared.b16 {%0,%1,%2,%3}, [%4];"
                 : "=r"(r[0]), "=r"(r[1]), "=r"(r[2]), "=r"(r[3])
                 : "r"(saddr));
}
__device__ __forceinline__ float ex2(float x) {
    float y;
    asm("ex2.approx.f32 %0, %1;" : "=f"(y) : "f"(x));
    return y;
}
__device__ __forceinline__ uint32_t ex2h2(float lo, float hi) {
    half2 h = __floats2half2_rn(lo, hi);
    uint32_t y;
    asm("ex2.approx.f16x2 %0, %1;" : "=r"(y) : "r"(*(uint32_t*)&h));
    return y;
}

// ---------------------------------------------------------------------------
// Merged prep: blocks [0, 8192) round+permute x -> g_xrh;
// blocks [8192, 12288) round Wq/Wk/Wv/Wf -> g_wh.  One launch.
// ---------------------------------------------------------------------------
__global__ void __launch_bounds__(256) prep_all(
    const float* __restrict__ x,
    const float* __restrict__ Wq, const float* __restrict__ Wk,
    const float* __restrict__ Wv, const float* __restrict__ Wf)
{
    const int bid = blockIdx.x;
    const int tid = threadIdx.x;
    if (bid < 8192) {
        const int idx = bid * 256 + tid;
        const int r  = idx >> 8;
        const int c4 = (idx & 255) * 4;
        const int bb = r >> 10, l = r & 1023;
        const int src = ((bb >> 2) << 12) + (l << 2) + (bb & 3);
        float4 v = *(const float4*)(x + (size_t)src * D_ + c4);
        half2 h0 = __floats2half2_rn(v.x, v.y);
        half2 h1 = __floats2half2_rn(v.z, v.w);
        uint2 u = make_uint2(*(uint32_t*)&h0, *(uint32_t*)&h1);
        *(uint2*)(g_xrh + (size_t)r * D_ + c4) = u;
    } else {
        const int wb  = bid - 8192;
        const int mat = wb >> 10;        // 0..3
        const int blk = wb & 1023;
        const float* src;
        switch (mat) {
            case 0: src = Wq; break;
            case 1: src = Wk; break;
            case 2: src = Wv; break;
            default: src = Wf; break;
        }
        const size_t off = (size_t)blk * 1024 + tid * 4;
        float4 v = *(const float4*)(src + off);
        half2 h0 = __floats2half2_rn(v.x, v.y);
        half2 h1 = __floats2half2_rn(v.z, v.w);
        uint2 u = make_uint2(*(uint32_t*)&h0, *(uint32_t*)&h1);
        *(uint2*)(&g_wh[mat][0] + off) = u;
    }
}

// ---------------------------------------------------------------------------
// fp16 warp-MMA GEMM v4: CTA 256x128, **16 warps** (512 thr) 4x4,
// warp tile 64x32, BK=64, 2-stage cp.async, 1 barrier/chunk, 1 CTA/SM.
// Same tile/traffic/barrier cadence as R16; only the warp count changes.
// ---------------------------------------------------------------------------
#define GROWB 144
#define ATILE (256 * GROWB)
#define BTILE (128 * GROWB)
#define STAGE (ATILE + BTILE)
#define GEMM_SMEM (2 * STAGE)
#define QSCALE 0.180336880f   // (1/8) * log2(e)

__global__ void __launch_bounds__(512, 1) gemm_mma(
    const float* __restrict__ bq, const float* __restrict__ bk,
    const float* __restrict__ bv,
    float* __restrict__ out_f32, int mode)
{
    extern __shared__ char dsmc[];
    const uint32_t sb = smem_u32(dsmc);

    const int tid  = threadIdx.x;
    const int wid  = tid >> 5;          // 0..15
    const int lane = tid & 31;
    const int lr   = lane >> 2;
    const int lc   = lane & 3;
    const int l7   = lane & 7;
    const int lb8  = (lane >> 3) & 1;
    const int lb16 = lane >> 4;
    const int wm0  = (wid >> 2) * 64;   // 0,64,128,192
    const int wn0  = (wid & 3) * 32;    // 0,32,64,96

    const __half* A; const __half* W; const float* bias;
    __half* outh = nullptr;
    float qscale = 1.0f;
    if (mode == 0) {
        A = g_xrh;
        W = &g_wh[blockIdx.z][0];
        if (blockIdx.z == 0)      { bias = bq; outh = g_qh; qscale = QSCALE; }
        else if (blockIdx.z == 1) { bias = bk; outh = g_kh; }
        else                      { bias = bv; outh = g_vh; }
    } else {
        A = g_ctxh; W = &g_wh[3][0]; bias = bq;
    }

    const int rm0 = blockIdx.y * 256;
    const int on0 = blockIdx.x * 128;

    // staging: r0 = tid>>3 in [0,64), seg = tid&7; thread owns A rows
    // r0+{0,64,128,192} and B rows r0+{0,64}; 6 cp16/chunk.
    const int r0  = tid >> 3;
    const int seg = tid & 7;
    const __half* arow[4];
    uint32_t asts[4];
    #pragma unroll
    for (int p = 0; p < 4; p++) {
        int r = rm0 + p * 64 + r0;
        int srcrow = r;
        if (mode == 1) {
            int b = r >> 12, s = r & 4095;
            srcrow = ((b << 2) + (s & 3)) * L_ + (s >> 2);
        }
        arow[p] = A + (size_t)srcrow * D_ + seg * 8;
        asts[p] = (uint32_t)((p * 64 + r0) * GROWB + seg * 16);
    }
    const __half* brow[2];
    uint32_t bsts[2];
    #pragma unroll
    for (int p = 0; p < 2; p++) {
        brow[p] = W + (size_t)(on0 + p * 64 + r0) * D_ + seg * 8;
        bsts[p] = (uint32_t)(ATILE + (p * 64 + r0) * GROWB + seg * 16);
    }

    // fragment base offsets (16B-aligned, conflict-free)
    const uint32_t aoff = (uint32_t)((wm0 + l7 + lb8 * 8) * GROWB + lb16 * 16);
    const uint32_t boff = (uint32_t)(ATILE + (wn0 + lb16 * 8 + l7) * GROWB + lb8 * 16);

    // prologue: chunk 0 -> buffer 0
    #pragma unroll
    for (int p = 0; p < 4; p++) cp16(sb + asts[p], arow[p]);
    #pragma unroll
    for (int p = 0; p < 2; p++) cp16(sb + bsts[p], brow[p]);
    CP_COMMIT();

    float acc[4][4][4] = {};

    for (int c = 0; c < 16; c++) {
        const int buf = c & 1;
        CP_WAIT(0);
        __syncthreads();   // chunk c visible; all warps done with buf (c-2)

        if (c < 15) {      // prefetch chunk c+1 into the other buffer
            const uint32_t ob = (uint32_t)(buf ^ 1) * STAGE;
            const int k1 = (c + 1) * 64;
            #pragma unroll
            for (int p = 0; p < 4; p++) cp16(sb + ob + asts[p], arow[p] + k1);
            #pragma unroll
            for (int p = 0; p < 2; p++) cp16(sb + ob + bsts[p], brow[p] + k1);
            CP_COMMIT();
        }

        const uint32_t base = sb + (uint32_t)buf * STAGE;

        #pragma unroll
        for (int kk = 0; kk < 4; kk++) {
            uint32_t a[4][4], b0[4], b1[4];
            #pragma unroll
            for (int mf = 0; mf < 4; mf++)
                ldm_x4(a[mf], base + aoff + mf * 16 * GROWB + kk * 32);
            ldm_x4(b0, base + boff + kk * 32);
            ldm_x4(b1, base + boff + 16 * GROWB + kk * 32);
            #pragma unroll
            for (int mf = 0; mf < 4; mf++) {
                mma_f16(acc[mf][0], a[mf], b0[0], b0[1]);
                mma_f16(acc[mf][1], a[mf], b0[2], b0[3]);
                mma_f16(acc[mf][2], a[mf], b1[0], b1[1]);
                mma_f16(acc[mf][3], a[mf], b1[2], b1[3]);
            }
        }
        // no trailing sync: next iteration's top sync covers buffer reuse
    }

    #pragma unroll
    for (int mf = 0; mf < 4; mf++) {
        const int row0 = rm0 + wm0 + mf * 16 + lr;
        #pragma unroll
        for (int nf = 0; nf < 4; nf++) {
            const int col = on0 + wn0 + nf * 8 + 2 * lc;
            const float bx = bias[col], by = bias[col + 1];
            float o00 = acc[mf][nf][0] + bx, o01 = acc[mf][nf][1] + by;
            float o10 = acc[mf][nf][2] + bx, o11 = acc[mf][nf][3] + by;
            if (mode == 0) {
                o00 *= qscale; o01 *= qscale; o10 *= qscale; o11 *= qscale;
                *(half2*)(outh + (size_t)row0 * D_ + col) =
                    __floats2half2_rn(o00, o01);
                *(half2*)(outh + (size_t)(row0 + 8) * D_ + col) =
                    __floats2half2_rn(o10, o11);
            } else {
                *(float2*)(out_f32 + (size_t)row0 * D_ + col) =
                    make_float2(o00, o01);
                *(float2*)(out_f32 + (size_t)(row0 + 8) * D_ + col) =
                    make_float2(o10, o11);
            }
        }
    }
}

// ---------------------------------------------------------------------------
// fp16 attention (R13 exact): FA2-style register P, 256 threads (8 warps),
// q-tile 128, key-tile 64 double-buffered, 2 CTAs/SM.
// SMEM: K0|K1|V0|V1 (64x144B each) + Q (128x144B) = 55296 B.
// ---------------------------------------------------------------------------
#define AROWB 144
#define KTB   (64 * AROWB)
#define QTB   (128 * AROWB)
#define QBASE (4 * KTB)
#define ATTN_SMEM (4 * KTB + QTB)

__global__ void __launch_bounds__(256, 2) attn_mma()
{
    extern __shared__ char dsmc[];
    const uint32_t sb = smem_u32(dsmc);

    const int tid  = threadIdx.x;
    const int wid  = tid >> 5;
    const int lane = tid & 31;
    const int lr   = lane >> 2;
    const int lc   = lane & 3;
    const int l7   = lane & 7;
    const int lb8  = (lane >> 3) & 1;
    const int lb16 = lane >> 4;
    const int bbh  = blockIdx.y;
    const int bb   = bbh >> 4;
    const int h    = bbh & 15;
    const int q0   = blockIdx.x * 128;

    const uint32_t ONES = 0x3C003C00u;

    const int krow = tid >> 2;
    const int kseg = tid & 3;
    const uint32_t kstg = (uint32_t)(krow * AROWB + kseg * 32);

    const __half* kg = g_kh + (size_t)(bb * L_) * D_ + h * DH_;
    const __half* vg = g_vh + (size_t)(bb * L_) * D_ + h * DH_;

    // prologue: K0/V0 in flight
    {
        const __half* kp = kg + (size_t)krow * D_ + kseg * 16;
        const __half* vp = vg + (size_t)krow * D_ + kseg * 16;
        cp16(sb + kstg, kp);
        cp16(sb + kstg + 16, kp + 8);
        cp16(sb + 2 * KTB + kstg, vp);
        cp16(sb + 2 * KTB + kstg + 16, vp + 8);
        CP_COMMIT();
    }

    // stage Q (128 x 64 halves, pre-scaled by 0.125*log2 e)
    {
        const int srow = tid >> 1;
        const __half* qg = g_qh + (size_t)(bb * L_ + q0 + srow) * D_ + h * DH_
                           + (tid & 1) * 32;
        char* dst = dsmc + QBASE + srow * AROWB + (tid & 1) * 64;
        #pragma unroll
        for (int j = 0; j < 4; j++)
            *(uint4*)(dst + j * 16) = *(const uint4*)(qg + j * 8);
    }
    __syncthreads();

    const uint32_t qoff = sb + QBASE
        + (uint32_t)((wid * 16 + l7 + lb8 * 8) * AROWB + lb16 * 16);
    const uint32_t koff = (uint32_t)((lb16 * 8 + l7) * AROWB + lb8 * 16);
    const uint32_t voff = (uint32_t)((l7 + lb8 * 8) * AROWB + lb16 * 16);

    uint32_t qa[4][4];
    #pragma unroll
    for (int kk = 0; kk < 4; kk++)
        ldm_x4(qa[kk], qoff + kk * 32);

    float O[8][4] = {};
    float lacc[4] = {};
    float m0 = -1e30f, m1 = -1e30f;

    for (int kt = 0; kt < 16; kt++) {
        const int buf = kt & 1;
        const uint32_t kbuf = sb + (uint32_t)buf * KTB;
        const uint32_t vbuf = sb + (uint32_t)(2 + buf) * KTB;

        CP_WAIT(0);
        __syncthreads();

        if (kt < 15) {
            const uint32_t ob = (uint32_t)(buf ^ 1) * KTB;
            const __half* kp = kg + (size_t)((kt + 1) * 64 + krow) * D_ + kseg * 16;
            const __half* vp = vg + (size_t)((kt + 1) * 64 + krow) * D_ + kseg * 16;
            cp16(sb + ob + kstg, kp);
            cp16(sb + ob + kstg + 16, kp + 8);
            cp16(sb + 2 * KTB + ob + kstg, vp);
            cp16(sb + 2 * KTB + ob + kstg + 16, vp + 8);
            CP_COMMIT();
        }

        // --- S = Qs @ K^T (16 x 64 per warp): 16 ldm + 32 MMA ---
        float s[8][4] = {};
        #pragma unroll
        for (int kk = 0; kk < 4; kk++) {
            #pragma unroll
            for (int np = 0; np < 4; np++) {
                uint32_t b[4];
                ldm_x4(b, kbuf + koff + (uint32_t)(np * 16 * AROWB + kk * 32));
                mma_f16(s[2 * np],     qa[kk], b[0], b[1]);
                mma_f16(s[2 * np + 1], qa[kk], b[2], b[3]);
            }
        }

        // --- online softmax (log2 domain), P kept in registers ---
        float ml0 = -1e30f, ml1 = -1e30f;
        #pragma unroll
        for (int nf = 0; nf < 8; nf++) {
            ml0 = fmaxf(ml0, fmaxf(s[nf][0], s[nf][1]));
            ml1 = fmaxf(ml1, fmaxf(s[nf][2], s[nf][3]));
        }
        ml0 = fmaxf(ml0, __shfl_xor_sync(0xffffffffu, ml0, 1));
        ml0 = fmaxf(ml0, __shfl_xor_sync(0xffffffffu, ml0, 2));
        ml1 = fmaxf(ml1, __shfl_xor_sync(0xffffffffu, ml1, 1));
        ml1 = fmaxf(ml1, __shfl_xor_sync(0xffffffffu, ml1, 2));
        const float mn0 = fmaxf(m0, ml0), mn1 = fmaxf(m1, ml1);
        const float c0 = ex2(m0 - mn0), c1 = ex2(m1 - mn1);
        m0 = mn0; m1 = mn1;

        uint32_t pl[8], ph[8];
        #pragma unroll
        for (int nf = 0; nf < 8; nf++) {
            pl[nf] = ex2h2(s[nf][0] - mn0, s[nf][1] - mn0);
            ph[nf] = ex2h2(s[nf][2] - mn1, s[nf][3] - mn1);
        }

        lacc[0] *= c0; lacc[1] *= c0; lacc[2] *= c1; lacc[3] *= c1;
        #pragma unroll
        for (int nf = 0; nf < 8; nf++) {
            O[nf][0] *= c0; O[nf][1] *= c0;
            O[nf][2] *= c1; O[nf][3] *= c1;
        }

        // --- l += P @ ones ---
        #pragma unroll
        for (int kk = 0; kk < 4; kk++) {
            const uint32_t a[4] = {pl[2*kk], ph[2*kk], pl[2*kk+1], ph[2*kk+1]};
            mma_f16(lacc, a, ONES, ONES);
        }

        // --- O += P @ V ---
        #pragma unroll
        for (int kk = 0; kk < 4; kk++) {
            const uint32_t a[4] = {pl[2*kk], ph[2*kk], pl[2*kk+1], ph[2*kk+1]};
            #pragma unroll
            for (int np = 0; np < 4; np++) {
                uint32_t b[4];
                ldm_x4t(b, vbuf + voff + (uint32_t)(kk * 16 * AROWB + np * 32));
                mma_f16(O[2 * np],     a, b[0], b[1]);
                mma_f16(O[2 * np + 1], a, b[2], b[3]);
            }
        }
    }

    const float inv0 = 1.f / lacc[0], inv1 = 1.f / lacc[2];
    __half* og = g_ctxh + (size_t)(bb * L_ + q0 + wid * 16) * D_ + h * DH_;
    #pragma unroll
    for (int nf = 0; nf < 8; nf++) {
        const int col = nf * 8 + 2 * lc;
        *(half2*)(og + (size_t)lr * D_ + col) =
            __floats2half2_rn(O[nf][0] * inv0, O[nf][1] * inv0);
        *(half2*)(og + (size_t)(lr + 8) * D_ + col) =
            __floats2half2_rn(O[nf][2] * inv1, O[nf][3] * inv1);
    }
}

// ---------------------------------------------------------------------------
// final = LayerNorm(atted + x) * gamma + beta.  float4 I/O version.
// ---------------------------------------------------------------------------
__global__ void __launch_bounds__(256) ln_kernel(
    const float* __restrict__ x,
    const float* __restrict__ atted_ext,
    const float* __restrict__ gamma, const float* __restrict__ beta,
    float* __restrict__ final_out)
{
    const float* atted = atted_ext;
    const int r = blockIdx.x;
    const int tid = threadIdx.x;
    const size_t base = (size_t)r * D_ + tid * 4;

    float4 xv = *(const float4*)(x + base);
    float4 av = *(const float4*)(atted + base);
    float4 v = make_float4(xv.x + av.x, xv.y + av.y, xv.z + av.z, xv.w + av.w);
    float s1 = v.x + v.y + v.z + v.w;
    float s2 = v.x*v.x + v.y*v.y + v.z*v.z + v.w*v.w;

    #pragma unroll
    for (int off = 16; off; off >>= 1) {
        s1 += __shfl_xor_sync(0xffffffffu, s1, off);
        s2 += __shfl_xor_sync(0xffffffffu, s2, off);
    }
    __shared__ float red[16];
    int warp = tid >> 5, lane = tid & 31;
    if (lane == 0) { red[warp] = s1; red[8 + warp] = s2; }
    __syncthreads();
    float t1 = 0.f, t2 = 0.f;
    #pragma unroll
    for (int w = 0; w < 8; w++) { t1 += red[w]; t2 += red[8 + w]; }
    float mu  = t1 * (1.f / 1024.f);
    float var = t2 * (1.f / 1024.f) - mu * mu;
    float rstd = rsqrtf(var + 1e-5f);

    float4 gv = *(const float4*)(gamma + tid * 4);
    float4 bv = *(const float4*)(beta + tid * 4);
    float4 o;
    o.x = (v.x - mu) * rstd * gv.x + bv.x;
    o.y = (v.y - mu) * rstd * gv.y + bv.y;
    o.z = (v.z - mu) * rstd * gv.z + bv.z;
    o.w = (v.w - mu) * rstd * gv.w + bv.w;
    *(float4*)(final_out + base) = o;
}

// ---------------------------------------------------------------------------
extern "C" void kernel_launch(void* const* d_in, const int* in_sizes, int n_in,
                              void* d_out, int out_size)
{
    (void)in_sizes; (void)n_in;
    const float* x     = (const float*)d_in[0];
    const float* Wq    = (const float*)d_in[1];
    const float* bq    = (const float*)d_in[2];
    const float* Wk    = (const float*)d_in[3];
    const float* bk    = (const float*)d_in[4];
    const float* Wv    = (const float*)d_in[5];
    const float* bv    = (const float*)d_in[6];
    const float* Wf    = (const float*)d_in[7];
    const float* bf    = (const float*)d_in[8];
    const float* gamma = (const float*)d_in[9];
    const float* beta  = (const float*)d_in[10];
    float* out = (float*)d_out;

    const long long both = 2LL * R_ * D_;
    float* atted = (out_size >= both) ? (out + (size_t)R_ * D_) : nullptr;
    if (!atted) {
        static float* h_atted_ptr = nullptr;
        if (!h_atted_ptr) cudaGetSymbolAddress((void**)&h_atted_ptr, g_atted);
        atted = h_atted_ptr;
    }

    static bool attr_set = false;
    if (!attr_set) {
        cudaFuncSetAttribute(attn_mma,
                             cudaFuncAttributeMaxDynamicSharedMemorySize,
                             ATTN_SMEM);
        cudaFuncSetAttribute(gemm_mma,
                             cudaFuncAttributeMaxDynamicSharedMemorySize,
                             GEMM_SMEM);
        attr_set = true;
    }

    prep_all<<<R_ * D_ / 1024 + 4 * D_ * D_ / 1024, 256>>>(x, Wq, Wk, Wv, Wf);

    gemm_mma<<<dim3(D_/128, R_/256, 3), 512, GEMM_SMEM>>>(
        bq, bk, bv, nullptr, 0);
    attn_mma<<<dim3(L_/128, B_ * DIL_ * H_), 256, ATTN_SMEM>>>();
    gemm_mma<<<dim3(D_/128, R_/256, 1), 512, GEMM_SMEM>>>(
        bf, nullptr, nullptr, atted, 1);
    ln_kernel<<<R_, 256>>>(x, atted, gamma, beta, out);
}